// round 6
// baseline (speedup 1.0000x reference)
#include <cuda_runtime.h>

// Problem constants (fixed by setup_inputs)
#define BS   8
#define NA   128
#define NC   256
#define ZZ   8
#define NT   3
#define NET  9
#define NETASK (BS*NC*3)   // 6144 edge tasks
#define NNODE  (BS*NA)     // 1024 node tasks
#define NTASKS (NETASK + NNODE)  // 7168
#define OUT_LOGPI (BS*NC*ZZ*ZZ*ZZ)   // 1048576

typedef unsigned long long u64;

// ---------------- device scratch (no allocations allowed) ----------------
__device__ __align__(16) float g_nf[NNODE*ZZ];
__device__ __align__(16) float g_ef[NETASK*64];
__device__ int g_ecnt[NET];          // zero at load; re-zeroed by assemble
__device__ int g_ncnt[NT];
__device__ int g_ebucket[NET*NETASK];
__device__ int g_nbucket[NT*NNODE];

static __device__ __forceinline__ int clampi(int v, int lo, int hi) {
    return v < lo ? lo : (v > hi ? hi : v);
}

// ---------------- packed f32x2 helpers (FFMA2) ----------------
static __device__ __forceinline__ u64 pack2(float a, float b) {
    u64 r; asm("mov.b64 %0, {%1, %2};" : "=l"(r) : "f"(a), "f"(b)); return r;
}
static __device__ __forceinline__ void unpack2(u64 v, float& a, float& b) {
    asm("mov.b64 {%0, %1}, %2;" : "=f"(a), "=f"(b) : "l"(v));
}
static __device__ __forceinline__ void ffma2(u64& d, u64 a, u64 b) {
    asm("fma.rn.f32x2 %0, %1, %2, %0;" : "+l"(d) : "l"(a), "l"(b));
}
static __device__ __forceinline__ void prefetchL2(const void* p) {
    asm volatile("prefetch.global.L2 [%0];" :: "l"(p));
}

// ---------------- kernel: bin tasks (types staged in smem) ----------------
// grid 28 x 256: exactly one task per thread.
__global__ __launch_bounds__(256) void bin_tasks_kernel(
    const int* __restrict__ types, const int* __restrict__ cni,
    const float* __restrict__ node_enc, const float* __restrict__ edge_enc)
{
    __shared__ int sT[NNODE];
    __shared__ int h[12];
    __shared__ int basev[12];
    int tid = threadIdx.x;
    int t = blockIdx.x * 256 + tid;

    // stage all node types (4KB) -> smem, coalesced
    {
        int4 v = ((const int4*)types)[tid];
        ((int4*)sT)[tid] = v;
    }
    if (tid < 12) h[tid] = 0;
    __syncthreads();

    int bk = -1, val = 0, pos = 0;
    const float* pfrow = 0;
    if (t < NETASK) {
        int b   = t / (NC*3);
        int rem = t - b*(NC*3);
        int c   = rem / 3;
        int p   = rem - 3*c;              // 0->(0,1) 1->(0,2) 2->(1,2)
        int a0  = (p == 2) ? 1 : 0;
        int a1  = (p == 0) ? 1 : 2;
        int i = clampi(cni[(b*NC + c)*3 + a0], 0, NA-1);
        int j = clampi(cni[(b*NC + c)*3 + a1], 0, NA-1);
        int ti = clampi(sT[b*NA + i], 0, NT-1);
        int tj = clampi(sT[b*NA + j], 0, NT-1);
        bk = tj*3 + ti;                   // emask: pa==type[j], pb==type[i]
        val = t;
        pfrow = edge_enc + ((size_t)(b*NA + i)*NA + j) * 64;
    } else if (t < NTASKS) {
        int nn = t - NETASK;
        bk = 9 + clampi(sT[nn], 0, NT-1);
        val = nn;
        pfrow = node_enc + (size_t)nn * 64;
    }
    if (bk >= 0) pos = atomicAdd(&h[bk], 1);
    __syncthreads();
    if (tid < 12 && h[tid] > 0) {
        basev[tid] = (tid < 9) ? atomicAdd(&g_ecnt[tid], h[tid])
                               : atomicAdd(&g_ncnt[tid-9], h[tid]);
    }
    __syncthreads();
    if (bk >= 0) {
        int base = basev[bk];
        if (bk < 9) g_ebucket[bk*NETASK + base + pos] = val;
        else        g_nbucket[(bk-9)*NNODE + base + pos] = val;
        // warm L2 with this task's 256B input row for the mlp gather
        prefetchL2(pfrow);
        prefetchL2(pfrow + 32);
    }
}

// ---------------- 32x64 @ 64x64 layer, 512 threads, 1 row x 4 cols/thread --
static __device__ __forceinline__ void layer64(const float* __restrict__ sIn,
                                               const float* __restrict__ sW,
                                               const float* __restrict__ sb,
                                               int row, int colb, u64 acc[2]) {
    ulonglong2 bv = *(const ulonglong2*)(sb + colb);
    acc[0] = bv.x; acc[1] = bv.y;
    const float* in = sIn + row*68;
    #pragma unroll
    for (int d0 = 0; d0 < 64; d0 += 4) {
        float4 x = *(const float4*)(in + d0);
        {
            ulonglong2 w = *(const ulonglong2*)(sW + (d0+0)*64 + colb);
            u64 a = pack2(x.x, x.x);
            ffma2(acc[0], a, w.x); ffma2(acc[1], a, w.y);
        }
        {
            ulonglong2 w = *(const ulonglong2*)(sW + (d0+1)*64 + colb);
            u64 a = pack2(x.y, x.y);
            ffma2(acc[0], a, w.x); ffma2(acc[1], a, w.y);
        }
        {
            ulonglong2 w = *(const ulonglong2*)(sW + (d0+2)*64 + colb);
            u64 a = pack2(x.z, x.z);
            ffma2(acc[0], a, w.x); ffma2(acc[1], a, w.y);
        }
        {
            ulonglong2 w = *(const ulonglong2*)(sW + (d0+3)*64 + colb);
            u64 a = pack2(x.w, x.w);
            ffma2(acc[0], a, w.x); ffma2(acc[1], a, w.y);
        }
    }
}

static __device__ __forceinline__ void store_relu(float* __restrict__ sOut,
                                                  int row, int colb, const u64 acc[2]) {
    float a, b, c, d;
    unpack2(acc[0], a, b); unpack2(acc[1], c, d);
    *(float4*)(sOut + row*68 + colb) =
        make_float4(fmaxf(a,0.f), fmaxf(b,0.f), fmaxf(c,0.f), fmaxf(d,0.f));
}

// ---------------- combined node+edge MLP kernel, 512 threads ----------------
__global__ __launch_bounds__(512) void mlp_kernel(
    const float* __restrict__ node_enc, const float* __restrict__ edge_enc,
    const int* __restrict__ cni,
    const float* __restrict__ nW0, const float* __restrict__ nb0,
    const float* __restrict__ nW1, const float* __restrict__ nb1,
    const float* __restrict__ nW2, const float* __restrict__ nb2,
    const float* __restrict__ eW0, const float* __restrict__ eb0,
    const float* __restrict__ eW1, const float* __restrict__ eb1,
    const float* __restrict__ eW2, const float* __restrict__ eb2)
{
    // ---- role mapping (uniform across threads) ----
    int bid = blockIdx.x;
    int g = -1, chunk = 0, acc = 0, cnt = 0;
    bool isEdge = true;
    #pragma unroll
    for (int t = 0; t < NET; t++) {
        int n = g_ecnt[t];
        int c = (n + 31) >> 5;
        if (g < 0 && bid < acc + c) { g = t; chunk = bid - acc; cnt = n; }
        acc += c;
    }
    if (g < 0) {
        isEdge = false;
        int nb = bid - acc; acc = 0;
        #pragma unroll
        for (int t = 0; t < NT; t++) {
            int n = g_ncnt[t];
            int c = (n + 31) >> 5;
            if (g < 0 && nb < acc + c) { g = t; chunk = nb - acc; cnt = n; }
            acc += c;
        }
        if (g < 0) return;
    }
    int base  = chunk * 32;
    int ntask = min(32, cnt - base);

    __shared__ __align__(16) float sW[64*64];
    __shared__ __align__(16) float sb0[64], sb1[64], sb2[64];
    __shared__ __align__(16) float sA[32*68];
    __shared__ __align__(16) float sB[32*68];
    __shared__ int s_idx[32];
    __shared__ int s_off[32];

    int tid  = threadIdx.x;
    int warp = tid >> 5, lane = tid & 31;
    int colb = (warp & 1) * 32 + (lane & 7) * 4;   // 4-col slab
    int row  = (warp >> 1) * 4 + (lane >> 3);      // one row 0..31

    const float *W0, *W1, *b0, *b1, *inBase;
    if (isEdge) {
        W0 = eW0 + g*4096; W1 = eW1 + g*4096;
        b0 = eb0 + g*64;   b1 = eb1 + g*64;
        inBase = edge_enc;
        if (tid < ntask) {
            int tt = g_ebucket[g*NETASK + base + tid];
            s_idx[tid] = tt;
            int b   = tt / (NC*3);
            int rem = tt - b*(NC*3);
            int c   = rem / 3;
            int p   = rem - 3*c;
            int a0  = (p == 2) ? 1 : 0;
            int a1  = (p == 0) ? 1 : 2;
            int i = clampi(cni[(b*NC + c)*3 + a0], 0, NA-1);
            int j = clampi(cni[(b*NC + c)*3 + a1], 0, NA-1);
            s_off[tid] = ((b*NA + i)*NA + j) * 64;
        }
    } else {
        W0 = nW0 + g*4096; W1 = nW1 + g*4096;
        b0 = nb0 + g*64;   b1 = nb1 + g*64;
        inBase = node_enc;
        if (tid < ntask) {
            int nn = g_nbucket[g*NNODE + base + tid];
            s_idx[tid] = nn;
            s_off[tid] = nn * 64;
        }
    }

    // stage W0 + biases (1024 float4 over 512 threads = 2 each)
    {
        const float4* w = (const float4*)W0;
        float4* sw = (float4*)sW;
        sw[tid]       = w[tid];
        sw[tid + 512] = w[tid + 512];
        if (tid < 64) { sb0[tid] = b0[tid]; sb1[tid] = b1[tid]; }
    }
    __syncthreads();

    // gather inputs (L2-warm from bin prefetch); prefetch W1 into regs
    float4 pw[2];
    {
        const float4* w = (const float4*)W1;
        pw[0] = w[tid]; pw[1] = w[tid + 512];
    }
    if (tid < ntask*16) {
        int s = tid >> 4, q = tid & 15;
        float4 v = *(const float4*)(inBase + (size_t)s_off[s] + q*4);
        *(float4*)(sA + s*68 + q*4) = v;
    }
    __syncthreads();

    u64 a2[2];
    layer64(sA, sW, sb0, row, colb, a2);            // layer 0
    __syncthreads();
    store_relu(sB, row, colb, a2);
    {   // W1 regs -> smem
        float4* sw = (float4*)sW;
        sw[tid] = pw[0]; sw[tid + 512] = pw[1];
    }
    // prefetch layer-2 weights
    if (isEdge) {
        const float4* w = (const float4*)(eW2 + g*4096);
        pw[0] = w[tid]; pw[1] = w[tid + 512];
        if (tid < 64) sb2[tid] = eb2[g*64 + tid];
    } else {
        if (tid < 128) pw[0] = ((const float4*)(nW2 + g*512))[tid];
        if (tid < 8)   sb2[tid] = nb2[g*8 + tid];
    }
    __syncthreads();

    layer64(sB, sW, sb1, row, colb, a2);            // layer 1
    __syncthreads();
    store_relu(sA, row, colb, a2);
    {   // W2 regs -> smem
        float4* sw = (float4*)sW;
        if (isEdge) { sw[tid] = pw[0]; sw[tid + 512] = pw[1]; }
        else if (tid < 128) sw[tid] = pw[0];
    }
    __syncthreads();

    if (isEdge) {                                    // layer 2 (edge, no relu)
        layer64(sA, sW, sb2, row, colb, a2);
        if (row < ntask) {
            float a, b, c, d;
            unpack2(a2[0], a, b); unpack2(a2[1], c, d);
            *(float4*)(g_ef + (size_t)s_idx[row]*64 + colb) = make_float4(a, b, c, d);
        }
    } else if (tid < 256) {                          // layer 2 (node, 64->8)
        int r = tid >> 3, col = tid & 7;
        float a = sb2[col];
        const float* in = sA + r*68;
        #pragma unroll 16
        for (int d = 0; d < 64; d++) a += in[d] * sW[d*8 + col];
        if (r < ntask) g_nf[(size_t)s_idx[r]*8 + col] = a;
    }
}

// ---------------- kernel: assemble logpi (+ z tail, + counter re-zero) ----
__global__ __launch_bounds__(256) void assemble_kernel(
    const int* __restrict__ cni, float* __restrict__ out, int writeZ)
{
    int tid = threadIdx.x;
    int sub = tid >> 6;                  // clique within block
    int t   = tid & 63;
    int cq  = blockIdx.x * 4 + sub;      // b*NC + c

    __shared__ float e[4][192];
    __shared__ float nf[4][3][8];

    size_t tbase = (size_t)cq * 192;
    e[sub][t]       = g_ef[tbase + t];
    e[sub][t + 64]  = g_ef[tbase + t + 64];
    e[sub][t + 128] = g_ef[tbase + t + 128];
    if (t < 24) {
        int k = t >> 3, zz = t & 7;
        int b = cq / NC;
        int node = clampi(cni[cq*3 + k], 0, NA-1);
        nf[sub][k][zz] = g_nf[((size_t)b*NA + node)*8 + zz];
    }

    if (blockIdx.x == 0) {               // housekeeping for next replay + z
        if (tid < NET) g_ecnt[tid] = 0;
        if (tid < NT)  g_ncnt[tid] = 0;
        if (writeZ) {
            for (int m = tid; m < 512; m += 256) {
                int i = m >> 6, j = (m >> 3) & 7, k = m & 7;
                float* p = out + OUT_LOGPI + (size_t)m*3;
                p[0] = (float)i; p[1] = (float)j; p[2] = (float)k;
            }
        }
    }
    __syncthreads();

    int z0 = t >> 3, z1 = t & 7;
    float bse = nf[sub][0][z0] + nf[sub][1][z1] + e[sub][z0*8 + z1];
    float r[8];
    #pragma unroll
    for (int z2 = 0; z2 < 8; z2++)
        r[z2] = bse + nf[sub][2][z2] + e[sub][64 + z0*8 + z2] + e[sub][128 + z1*8 + z2];
    float* op = out + (size_t)cq*512 + t*8;
    *(float4*)op       = make_float4(r[0], r[1], r[2], r[3]);
    *(float4*)(op + 4) = make_float4(r[4], r[5], r[6], r[7]);
}

// ---------------- launch ----------------
extern "C" void kernel_launch(void* const* d_in, const int* in_sizes, int n_in,
                              void* d_out, int out_size) {
    const int*   types    = (const int*)d_in[0];
    const float* node_enc = (const float*)d_in[1];
    const float* edge_enc = (const float*)d_in[2];
    const int*   cni      = (const int*)d_in[4];
    const float* nW0 = (const float*)d_in[6];
    const float* nb0 = (const float*)d_in[7];
    const float* nW1 = (const float*)d_in[8];
    const float* nb1 = (const float*)d_in[9];
    const float* nW2 = (const float*)d_in[10];
    const float* nb2 = (const float*)d_in[11];
    const float* eW0 = (const float*)d_in[12];
    const float* eb0 = (const float*)d_in[13];
    const float* eW1 = (const float*)d_in[14];
    const float* eb1 = (const float*)d_in[15];
    const float* eW2 = (const float*)d_in[16];
    const float* eb2 = (const float*)d_in[17];
    float* out = (float*)d_out;

    int writeZ = (out_size >= OUT_LOGPI + 512*3) ? 1 : 0;

    bin_tasks_kernel<<<28, 256>>>(types, cni, node_enc, edge_enc);
    mlp_kernel<<<240, 512>>>(node_enc, edge_enc, cni,
                             nW0, nb0, nW1, nb1, nW2, nb2,
                             eW0, eb0, eW1, eb1, eW2, eb2);
    assemble_kernel<<<BS * NC / 4, 256>>>(cni, out, writeZ);
}

// round 7
// speedup vs baseline: 1.1013x; 1.1013x over previous
#include <cuda_runtime.h>

// Problem constants (fixed by setup_inputs)
#define BS   8
#define NA   128
#define NC   256
#define ZZ   8
#define NT   3
#define NET  9
#define NETASK (BS*NC*3)   // 6144 edge tasks
#define NNODE  (BS*NA)     // 1024 node tasks
#define NTASKS (NETASK + NNODE)  // 7168
#define OUT_LOGPI (BS*NC*ZZ*ZZ*ZZ)   // 1048576
#define ECH 32             // chunks per edge type (capacity 1024 tasks)
#define NCH 16             // chunks per node type (capacity 512 tasks)
#define MLP_GRID (NET*ECH + NT*NCH)  // 336

typedef unsigned long long u64;

// ---------------- device scratch (no allocations allowed) ----------------
__device__ __align__(16) float g_nf[NNODE*ZZ];
__device__ __align__(16) float g_ef[NETASK*64];
__device__ int g_ecnt[NET];          // zero at load; re-zeroed by assemble
__device__ int g_ncnt[NT];
__device__ int g_ebucket[NET*NETASK];
__device__ int g_nbucket[NT*NNODE];

static __device__ __forceinline__ int clampi(int v, int lo, int hi) {
    return v < lo ? lo : (v > hi ? hi : v);
}

// ---------------- packed f32x2 helpers (FFMA2) ----------------
static __device__ __forceinline__ u64 pack2(float a, float b) {
    u64 r; asm("mov.b64 %0, {%1, %2};" : "=l"(r) : "f"(a), "f"(b)); return r;
}
static __device__ __forceinline__ void unpack2(u64 v, float& a, float& b) {
    asm("mov.b64 {%0, %1}, %2;" : "=f"(a), "=f"(b) : "l"(v));
}
static __device__ __forceinline__ void ffma2(u64& d, u64 a, u64 b) {
    asm("fma.rn.f32x2 %0, %1, %2, %0;" : "+l"(d) : "l"(a), "l"(b));
}
static __device__ __forceinline__ void prefetchL2(const void* p) {
    asm volatile("prefetch.global.L2 [%0];" :: "l"(p));
}

// ---------------- kernel: bin tasks (types staged in smem) ----------------
__global__ __launch_bounds__(256) void bin_tasks_kernel(
    const int* __restrict__ types, const int* __restrict__ cni,
    const float* __restrict__ node_enc, const float* __restrict__ edge_enc)
{
    __shared__ int sT[NNODE];
    __shared__ int h[12];
    __shared__ int basev[12];
    int tid = threadIdx.x;
    int t = blockIdx.x * 256 + tid;

    {
        int4 v = ((const int4*)types)[tid];
        ((int4*)sT)[tid] = v;
    }
    if (tid < 12) h[tid] = 0;
    __syncthreads();

    int bk = -1, val = 0, pos = 0;
    const float* pfrow = 0;
    if (t < NETASK) {
        int b   = t / (NC*3);
        int rem = t - b*(NC*3);
        int c   = rem / 3;
        int p   = rem - 3*c;              // 0->(0,1) 1->(0,2) 2->(1,2)
        int a0  = (p == 2) ? 1 : 0;
        int a1  = (p == 0) ? 1 : 2;
        int i = clampi(cni[(b*NC + c)*3 + a0], 0, NA-1);
        int j = clampi(cni[(b*NC + c)*3 + a1], 0, NA-1);
        int ti = clampi(sT[b*NA + i], 0, NT-1);
        int tj = clampi(sT[b*NA + j], 0, NT-1);
        bk = tj*3 + ti;                   // emask: pa==type[j], pb==type[i]
        val = t;
        pfrow = edge_enc + ((size_t)(b*NA + i)*NA + j) * 64;
    } else if (t < NTASKS) {
        int nn = t - NETASK;
        bk = 9 + clampi(sT[nn], 0, NT-1);
        val = nn;
        pfrow = node_enc + (size_t)nn * 64;
    }
    if (bk >= 0) pos = atomicAdd(&h[bk], 1);
    __syncthreads();
    if (tid < 12 && h[tid] > 0) {
        basev[tid] = (tid < 9) ? atomicAdd(&g_ecnt[tid], h[tid])
                               : atomicAdd(&g_ncnt[tid-9], h[tid]);
    }
    __syncthreads();
    if (bk >= 0) {
        int base = basev[bk];
        if (bk < 9) g_ebucket[bk*NETASK + base + pos] = val;
        else        g_nbucket[(bk-9)*NNODE + base + pos] = val;
    }
    // make writes visible, then release the dependent (PDL) mlp launch
    __threadfence();
    cudaTriggerProgrammaticLaunchCompletion();
    // warm L2 for the mlp gathers (after trigger; fire-and-forget)
    if (bk >= 0) { prefetchL2(pfrow); prefetchL2(pfrow + 32); }
}

// ---------------- 32x64 @ 64x64 layer, 256 thr, 2 rows x 4 cols/thread ----
static __device__ __forceinline__ void layer64(const float* __restrict__ sIn,
                                               const float* __restrict__ sW,
                                               const float* __restrict__ sb,
                                               int r0, int colb, u64 acc[4]) {
    ulonglong2 bv = *(const ulonglong2*)(sb + colb);
    acc[0] = bv.x; acc[1] = bv.y; acc[2] = bv.x; acc[3] = bv.y;
    const float* in0 = sIn + r0*68;
    const float* in1 = sIn + (r0+4)*68;
    #pragma unroll
    for (int d0 = 0; d0 < 64; d0 += 4) {
        float4 x0 = *(const float4*)(in0 + d0);
        float4 x1 = *(const float4*)(in1 + d0);
        {
            ulonglong2 w = *(const ulonglong2*)(sW + (d0+0)*64 + colb);
            u64 a0 = pack2(x0.x, x0.x), a1 = pack2(x1.x, x1.x);
            ffma2(acc[0], a0, w.x); ffma2(acc[1], a0, w.y);
            ffma2(acc[2], a1, w.x); ffma2(acc[3], a1, w.y);
        }
        {
            ulonglong2 w = *(const ulonglong2*)(sW + (d0+1)*64 + colb);
            u64 a0 = pack2(x0.y, x0.y), a1 = pack2(x1.y, x1.y);
            ffma2(acc[0], a0, w.x); ffma2(acc[1], a0, w.y);
            ffma2(acc[2], a1, w.x); ffma2(acc[3], a1, w.y);
        }
        {
            ulonglong2 w = *(const ulonglong2*)(sW + (d0+2)*64 + colb);
            u64 a0 = pack2(x0.z, x0.z), a1 = pack2(x1.z, x1.z);
            ffma2(acc[0], a0, w.x); ffma2(acc[1], a0, w.y);
            ffma2(acc[2], a1, w.x); ffma2(acc[3], a1, w.y);
        }
        {
            ulonglong2 w = *(const ulonglong2*)(sW + (d0+3)*64 + colb);
            u64 a0 = pack2(x0.w, x0.w), a1 = pack2(x1.w, x1.w);
            ffma2(acc[0], a0, w.x); ffma2(acc[1], a0, w.y);
            ffma2(acc[2], a1, w.x); ffma2(acc[3], a1, w.y);
        }
    }
}

static __device__ __forceinline__ void store_relu(float* __restrict__ sOut,
                                                  int r0, int colb, const u64 acc[4]) {
    float a, b, c, d;
    unpack2(acc[0], a, b); unpack2(acc[1], c, d);
    *(float4*)(sOut + r0*68 + colb) =
        make_float4(fmaxf(a,0.f), fmaxf(b,0.f), fmaxf(c,0.f), fmaxf(d,0.f));
    unpack2(acc[2], a, b); unpack2(acc[3], c, d);
    *(float4*)(sOut + (r0+4)*68 + colb) =
        make_float4(fmaxf(a,0.f), fmaxf(b,0.f), fmaxf(c,0.f), fmaxf(d,0.f));
}

// ---------------- MLP kernel: static role map, PDL-overlapped prologue -----
__global__ __launch_bounds__(256) void mlp_kernel(
    const float* __restrict__ node_enc, const float* __restrict__ edge_enc,
    const int* __restrict__ cni,
    const float* __restrict__ nW0, const float* __restrict__ nb0,
    const float* __restrict__ nW1, const float* __restrict__ nb1,
    const float* __restrict__ nW2, const float* __restrict__ nb2,
    const float* __restrict__ eW0, const float* __restrict__ eb0,
    const float* __restrict__ eW1, const float* __restrict__ eb1,
    const float* __restrict__ eW2, const float* __restrict__ eb2)
{
    __shared__ __align__(16) float sW[64*64];
    __shared__ __align__(16) float sb0[64], sb1[64], sb2[64];
    __shared__ __align__(16) float sA[32*68];
    __shared__ __align__(16) float sB[32*68];
    __shared__ int s_idx[32];
    __shared__ int s_off[32];

    int tid  = threadIdx.x;
    int bid  = blockIdx.x;

    // ---- static role map (no dependence on bin results) ----
    bool isEdge = bid < NET*ECH;
    int g, chunk;
    if (isEdge) { g = bid >> 5; chunk = bid & (ECH-1); }
    else { int nb = bid - NET*ECH; g = nb >> 4; chunk = nb & (NCH-1); }
    int base = chunk * 32;

    int warp = tid >> 5, lane = tid & 31;
    int colb = (warp & 1) * 32 + (lane & 7) * 4;
    int r0   = (warp >> 1) * 8 + (lane >> 3);

    const float *W0, *W1, *b0, *b1, *inBase;
    if (isEdge) {
        W0 = eW0 + g*4096; W1 = eW1 + g*4096;
        b0 = eb0 + g*64;   b1 = eb1 + g*64;
        inBase = edge_enc;
    } else {
        W0 = nW0 + g*4096; W1 = nW1 + g*4096;
        b0 = nb0 + g*64;   b1 = nb1 + g*64;
        inBase = node_enc;
    }

    // ---- PRE-SYNC: stage all weights/biases (pure inputs) ----
    {
        const float4* w = (const float4*)W0;
        float4* sw = (float4*)sW;
        #pragma unroll
        for (int k = 0; k < 4; k++) sw[tid + 256*k] = w[tid + 256*k];
        if (tid < 64) { sb0[tid] = b0[tid]; sb1[tid] = b1[tid]; }
    }
    float4 pw[4];
    {
        const float4* w = (const float4*)W1;
        #pragma unroll
        for (int k = 0; k < 4; k++) pw[k] = w[tid + 256*k];
    }
    if (isEdge) {
        if (tid < 64) sb2[tid] = eb2[g*64 + tid];
    } else {
        if (tid < 8) sb2[tid] = nb2[g*8 + tid];
    }

    // ---- wait for bin results ----
    cudaGridDependencySynchronize();

    int cnt = isEdge ? __ldcg(&g_ecnt[g]) : __ldcg(&g_ncnt[g]);  // off critical path

    // speculative bucket + offset decode (memory-safe; guarded at stores)
    if (tid < 32) {
        if (isEdge) {
            int tt = __ldcg(&g_ebucket[g*NETASK + base + tid]);
            s_idx[tid] = tt;
            int b   = tt / (NC*3);
            int rem = tt - b*(NC*3);
            int c   = rem / 3;
            int p   = rem - 3*c;
            int a0  = (p == 2) ? 1 : 0;
            int a1  = (p == 0) ? 1 : 2;
            int i = clampi(cni[(b*NC + c)*3 + a0], 0, NA-1);
            int j = clampi(cni[(b*NC + c)*3 + a1], 0, NA-1);
            s_off[tid] = ((b*NA + i)*NA + j) * 64;
        } else {
            int nn = __ldcg(&g_nbucket[g*NNODE + base + tid]);
            s_idx[tid] = nn;
            s_off[tid] = nn * 64;
        }
    }
    __syncthreads();

    // gather all 32 rows unconditionally (stale rows computed then discarded)
    {
        int s = tid >> 4, q = tid & 15;
        *(float4*)(sA + s*68 + q*4)      = *(const float4*)(inBase + (size_t)s_off[s]      + q*4);
        *(float4*)(sA + (s+16)*68 + q*4) = *(const float4*)(inBase + (size_t)s_off[s+16]   + q*4);
    }
    __syncthreads();

    int ntask = min(32, cnt - base);     // may be <= 0; only guards stores

    u64 a4[4];
    layer64(sA, sW, sb0, r0, colb, a4);              // layer 0
    __syncthreads();
    store_relu(sB, r0, colb, a4);
    {
        float4* sw = (float4*)sW;
        #pragma unroll
        for (int k = 0; k < 4; k++) sw[tid + 256*k] = pw[k];
    }
    if (isEdge) {
        const float4* w = (const float4*)(eW2 + g*4096);
        #pragma unroll
        for (int k = 0; k < 4; k++) pw[k] = w[tid + 256*k];
    } else {
        if (tid < 128) pw[0] = ((const float4*)(nW2 + g*512))[tid];
    }
    __syncthreads();

    layer64(sB, sW, sb1, r0, colb, a4);              // layer 1
    __syncthreads();
    store_relu(sA, r0, colb, a4);
    {
        float4* sw = (float4*)sW;
        if (isEdge) {
            #pragma unroll
            for (int k = 0; k < 4; k++) sw[tid + 256*k] = pw[k];
        } else {
            if (tid < 128) sw[tid] = pw[0];
        }
    }
    __syncthreads();

    if (isEdge) {                                     // layer 2 (edge, no relu)
        layer64(sA, sW, sb2, r0, colb, a4);
        float a, b, c, d;
        if (r0 < ntask) {
            unpack2(a4[0], a, b); unpack2(a4[1], c, d);
            *(float4*)(g_ef + (size_t)s_idx[r0]*64 + colb) = make_float4(a, b, c, d);
        }
        if (r0 + 4 < ntask) {
            unpack2(a4[2], a, b); unpack2(a4[3], c, d);
            *(float4*)(g_ef + (size_t)s_idx[r0+4]*64 + colb) = make_float4(a, b, c, d);
        }
    } else {                                          // layer 2 (node, 64->8)
        int row = tid >> 3, col = tid & 7;
        float a = sb2[col];
        const float* in = sA + row*68;
        #pragma unroll 16
        for (int d = 0; d < 64; d++) a += in[d] * sW[d*8 + col];
        if (row < ntask) g_nf[(size_t)s_idx[row]*8 + col] = a;
    }
    __threadfence();
    cudaTriggerProgrammaticLaunchCompletion();
}

// ---------------- kernel: assemble logpi (PDL; z-tail pre-sync) ----------
__global__ __launch_bounds__(256) void assemble_kernel(
    const int* __restrict__ cni, float* __restrict__ out, int writeZ)
{
    int tid = threadIdx.x;
    int sub = tid >> 6;
    int t   = tid & 63;
    int cq  = blockIdx.x * 4 + sub;

    __shared__ float e[4][192];
    __shared__ float nf[4][3][8];

    // PRE-SYNC: z tail (out region untouched by mlp)
    if (blockIdx.x == 0 && writeZ) {
        for (int m = tid; m < 512; m += 256) {
            int i = m >> 6, j = (m >> 3) & 7, k = m & 7;
            float* p = out + OUT_LOGPI + (size_t)m*3;
            p[0] = (float)i; p[1] = (float)j; p[2] = (float)k;
        }
    }

    cudaGridDependencySynchronize();

    // post-sync: safe to reset counters for the next replay (mlp grid done)
    if (blockIdx.x == 0) {
        if (tid < NET) g_ecnt[tid] = 0;
        if (tid < NT)  g_ncnt[tid] = 0;
    }

    size_t tbase = (size_t)cq * 192;
    e[sub][t]       = __ldcg(&g_ef[tbase + t]);
    e[sub][t + 64]  = __ldcg(&g_ef[tbase + t + 64]);
    e[sub][t + 128] = __ldcg(&g_ef[tbase + t + 128]);
    if (t < 24) {
        int k = t >> 3, zz = t & 7;
        int b = cq / NC;
        int node = clampi(cni[cq*3 + k], 0, NA-1);
        nf[sub][k][zz] = __ldcg(&g_nf[((size_t)b*NA + node)*8 + zz]);
    }
    __syncthreads();

    int z0 = t >> 3, z1 = t & 7;
    float bse = nf[sub][0][z0] + nf[sub][1][z1] + e[sub][z0*8 + z1];
    float r[8];
    #pragma unroll
    for (int z2 = 0; z2 < 8; z2++)
        r[z2] = bse + nf[sub][2][z2] + e[sub][64 + z0*8 + z2] + e[sub][128 + z1*8 + z2];
    float* op = out + (size_t)cq*512 + t*8;
    *(float4*)op       = make_float4(r[0], r[1], r[2], r[3]);
    *(float4*)(op + 4) = make_float4(r[4], r[5], r[6], r[7]);
}

// ---------------- launch ----------------
extern "C" void kernel_launch(void* const* d_in, const int* in_sizes, int n_in,
                              void* d_out, int out_size) {
    const int*   types    = (const int*)d_in[0];
    const float* node_enc = (const float*)d_in[1];
    const float* edge_enc = (const float*)d_in[2];
    const int*   cni      = (const int*)d_in[4];
    const float* nW0 = (const float*)d_in[6];
    const float* nb0 = (const float*)d_in[7];
    const float* nW1 = (const float*)d_in[8];
    const float* nb1 = (const float*)d_in[9];
    const float* nW2 = (const float*)d_in[10];
    const float* nb2 = (const float*)d_in[11];
    const float* eW0 = (const float*)d_in[12];
    const float* eb0 = (const float*)d_in[13];
    const float* eW1 = (const float*)d_in[14];
    const float* eb1 = (const float*)d_in[15];
    const float* eW2 = (const float*)d_in[16];
    const float* eb2 = (const float*)d_in[17];
    float* out = (float*)d_out;

    int writeZ = (out_size >= OUT_LOGPI + 512*3) ? 1 : 0;

    bin_tasks_kernel<<<28, 256>>>(types, cni, node_enc, edge_enc);

    cudaLaunchAttribute attr[1];
    attr[0].id = cudaLaunchAttributeProgrammaticStreamSerialization;
    attr[0].val.programmaticStreamSerializationAllowed = 1;

    {
        cudaLaunchConfig_t cfg = {};
        cfg.gridDim  = dim3(MLP_GRID, 1, 1);
        cfg.blockDim = dim3(256, 1, 1);
        cfg.stream   = 0;
        cfg.attrs    = attr;
        cfg.numAttrs = 1;
        cudaLaunchKernelEx(&cfg, mlp_kernel, node_enc, edge_enc, cni,
                           nW0, nb0, nW1, nb1, nW2, nb2,
                           eW0, eb0, eW1, eb1, eW2, eb2);
    }
    {
        cudaLaunchConfig_t cfg = {};
        cfg.gridDim  = dim3(BS * NC / 4, 1, 1);
        cfg.blockDim = dim3(256, 1, 1);
        cfg.stream   = 0;
        cfg.attrs    = attr;
        cfg.numAttrs = 1;
        cudaLaunchKernelEx(&cfg, assemble_kernel, cni, out, writeZ);
    }
}

// round 8
// speedup vs baseline: 1.1648x; 1.0577x over previous
#include <cuda_runtime.h>

// Problem constants (fixed by setup_inputs)
#define BS   8
#define NA   128
#define NC   256
#define ZZ   8
#define NT   3
#define NET  9
#define NETASK (BS*NC*3)   // 6144 edge tasks
#define NNODE  (BS*NA)     // 1024 node tasks
#define NTASKS (NETASK + NNODE)  // 7168
#define OUT_LOGPI (BS*NC*ZZ*ZZ*ZZ)   // 1048576
#define ECH 32             // chunks per edge type (capacity 1024 tasks)
#define NCH 16             // chunks per node type (capacity 512 tasks)
#define MLP_GRID (NET*ECH + NT*NCH)  // 336

typedef unsigned long long u64;

// ---------------- device scratch (no allocations allowed) ----------------
__device__ __align__(16) float g_nf[NNODE*ZZ];
__device__ __align__(16) float g_ef[NETASK*64];
__device__ int g_ecnt[NET];          // zero at load; re-zeroed by assemble
__device__ int g_ncnt[NT];
__device__ int g_ebucket[NET*NETASK];   // task id
__device__ int g_eoff[NET*NETASK];      // precomputed edge_enc offset
__device__ int g_nbucket[NT*NNODE];     // node id
__device__ int g_noff[NT*NNODE];        // precomputed node_enc offset

static __device__ __forceinline__ int clampi(int v, int lo, int hi) {
    return v < lo ? lo : (v > hi ? hi : v);
}

// ---------------- packed f32x2 helpers (FFMA2) ----------------
static __device__ __forceinline__ u64 pack2(float a, float b) {
    u64 r; asm("mov.b64 %0, {%1, %2};" : "=l"(r) : "f"(a), "f"(b)); return r;
}
static __device__ __forceinline__ void unpack2(u64 v, float& a, float& b) {
    asm("mov.b64 {%0, %1}, %2;" : "=f"(a), "=f"(b) : "l"(v));
}
static __device__ __forceinline__ void ffma2(u64& d, u64 a, u64 b) {
    asm("fma.rn.f32x2 %0, %1, %2, %0;" : "+l"(d) : "l"(a), "l"(b));
}
static __device__ __forceinline__ void prefetchL2(const void* p) {
    asm volatile("prefetch.global.L2 [%0];" :: "l"(p));
}

// ---------------- kernel: bin tasks (types staged in smem) ----------------
__global__ __launch_bounds__(256) void bin_tasks_kernel(
    const int* __restrict__ types, const int* __restrict__ cni,
    const float* __restrict__ node_enc, const float* __restrict__ edge_enc)
{
    __shared__ int sT[NNODE];
    __shared__ int h[12];
    __shared__ int basev[12];
    int tid = threadIdx.x;
    int t = blockIdx.x * 256 + tid;

    {
        int4 v = ((const int4*)types)[tid];
        ((int4*)sT)[tid] = v;
    }
    if (tid < 12) h[tid] = 0;
    __syncthreads();

    int bk = -1, val = 0, off = 0, pos = 0;
    const float* pfrow = 0;
    if (t < NETASK) {
        int b   = t / (NC*3);
        int rem = t - b*(NC*3);
        int c   = rem / 3;
        int p   = rem - 3*c;              // 0->(0,1) 1->(0,2) 2->(1,2)
        int a0  = (p == 2) ? 1 : 0;
        int a1  = (p == 0) ? 1 : 2;
        int i = clampi(cni[(b*NC + c)*3 + a0], 0, NA-1);
        int j = clampi(cni[(b*NC + c)*3 + a1], 0, NA-1);
        int ti = clampi(sT[b*NA + i], 0, NT-1);
        int tj = clampi(sT[b*NA + j], 0, NT-1);
        bk  = tj*3 + ti;                  // emask: pa==type[j], pb==type[i]
        val = t;
        off = ((b*NA + i)*NA + j) * 64;
        pfrow = edge_enc + (size_t)off;
    } else if (t < NTASKS) {
        int nn = t - NETASK;
        bk  = 9 + clampi(sT[nn], 0, NT-1);
        val = nn;
        off = nn * 64;
        pfrow = node_enc + (size_t)off;
    }
    if (bk >= 0) pos = atomicAdd(&h[bk], 1);
    __syncthreads();
    if (tid < 12 && h[tid] > 0) {
        basev[tid] = (tid < 9) ? atomicAdd(&g_ecnt[tid], h[tid])
                               : atomicAdd(&g_ncnt[tid-9], h[tid]);
    }
    __syncthreads();
    if (bk >= 0) {
        int base = basev[bk];
        if (bk < 9) {
            g_ebucket[bk*NETASK + base + pos] = val;
            g_eoff   [bk*NETASK + base + pos] = off;
        } else {
            g_nbucket[(bk-9)*NNODE + base + pos] = val;
            g_noff   [(bk-9)*NNODE + base + pos] = off;
        }
    }
    // make writes visible, then release the dependent (PDL) mlp launch
    __threadfence();
    cudaTriggerProgrammaticLaunchCompletion();
    // warm L2 for the mlp gathers (after trigger; fire-and-forget)
    if (bk >= 0) { prefetchL2(pfrow); prefetchL2(pfrow + 32); }
}

// ---------------- 32x64 @ 64x64 layer, 256 thr, 2 rows x 4 cols/thread ----
static __device__ __forceinline__ void layer64(const float* __restrict__ sIn,
                                               const float* __restrict__ sW,
                                               const float* __restrict__ sb,
                                               int r0, int colb, u64 acc[4]) {
    ulonglong2 bv = *(const ulonglong2*)(sb + colb);
    acc[0] = bv.x; acc[1] = bv.y; acc[2] = bv.x; acc[3] = bv.y;
    const float* in0 = sIn + r0*68;
    const float* in1 = sIn + (r0+4)*68;
    #pragma unroll
    for (int d0 = 0; d0 < 64; d0 += 4) {
        float4 x0 = *(const float4*)(in0 + d0);
        float4 x1 = *(const float4*)(in1 + d0);
        {
            ulonglong2 w = *(const ulonglong2*)(sW + (d0+0)*64 + colb);
            u64 a0 = pack2(x0.x, x0.x), a1 = pack2(x1.x, x1.x);
            ffma2(acc[0], a0, w.x); ffma2(acc[1], a0, w.y);
            ffma2(acc[2], a1, w.x); ffma2(acc[3], a1, w.y);
        }
        {
            ulonglong2 w = *(const ulonglong2*)(sW + (d0+1)*64 + colb);
            u64 a0 = pack2(x0.y, x0.y), a1 = pack2(x1.y, x1.y);
            ffma2(acc[0], a0, w.x); ffma2(acc[1], a0, w.y);
            ffma2(acc[2], a1, w.x); ffma2(acc[3], a1, w.y);
        }
        {
            ulonglong2 w = *(const ulonglong2*)(sW + (d0+2)*64 + colb);
            u64 a0 = pack2(x0.z, x0.z), a1 = pack2(x1.z, x1.z);
            ffma2(acc[0], a0, w.x); ffma2(acc[1], a0, w.y);
            ffma2(acc[2], a1, w.x); ffma2(acc[3], a1, w.y);
        }
        {
            ulonglong2 w = *(const ulonglong2*)(sW + (d0+3)*64 + colb);
            u64 a0 = pack2(x0.w, x0.w), a1 = pack2(x1.w, x1.w);
            ffma2(acc[0], a0, w.x); ffma2(acc[1], a0, w.y);
            ffma2(acc[2], a1, w.x); ffma2(acc[3], a1, w.y);
        }
    }
}

static __device__ __forceinline__ void store_relu(float* __restrict__ sOut,
                                                  int r0, int colb, const u64 acc[4]) {
    float a, b, c, d;
    unpack2(acc[0], a, b); unpack2(acc[1], c, d);
    *(float4*)(sOut + r0*68 + colb) =
        make_float4(fmaxf(a,0.f), fmaxf(b,0.f), fmaxf(c,0.f), fmaxf(d,0.f));
    unpack2(acc[2], a, b); unpack2(acc[3], c, d);
    *(float4*)(sOut + (r0+4)*68 + colb) =
        make_float4(fmaxf(a,0.f), fmaxf(b,0.f), fmaxf(c,0.f), fmaxf(d,0.f));
}

// ---------------- MLP kernel: static role map, PDL-overlapped prologue -----
__global__ __launch_bounds__(256) void mlp_kernel(
    const float* __restrict__ node_enc, const float* __restrict__ edge_enc,
    const float* __restrict__ nW0, const float* __restrict__ nb0,
    const float* __restrict__ nW1, const float* __restrict__ nb1,
    const float* __restrict__ nW2, const float* __restrict__ nb2,
    const float* __restrict__ eW0, const float* __restrict__ eb0,
    const float* __restrict__ eW1, const float* __restrict__ eb1,
    const float* __restrict__ eW2, const float* __restrict__ eb2)
{
    __shared__ __align__(16) float sW[64*64];
    __shared__ __align__(16) float sb0[64], sb1[64], sb2[64];
    __shared__ __align__(16) float sA[32*68];
    __shared__ __align__(16) float sB[32*68];
    __shared__ int s_idx[32];
    __shared__ int s_off[32];

    int tid  = threadIdx.x;
    int bid  = blockIdx.x;

    // ---- static role map (no dependence on bin results) ----
    bool isEdge = bid < NET*ECH;
    int g, chunk;
    if (isEdge) { g = bid >> 5; chunk = bid & (ECH-1); }
    else { int nb = bid - NET*ECH; g = nb >> 4; chunk = nb & (NCH-1); }
    int base = chunk * 32;

    int warp = tid >> 5, lane = tid & 31;
    int colb = (warp & 1) * 32 + (lane & 7) * 4;
    int r0   = (warp >> 1) * 8 + (lane >> 3);

    const float *W0, *W1, *b0, *b1, *inBase;
    if (isEdge) {
        W0 = eW0 + g*4096; W1 = eW1 + g*4096;
        b0 = eb0 + g*64;   b1 = eb1 + g*64;
        inBase = edge_enc;
    } else {
        W0 = nW0 + g*4096; W1 = nW1 + g*4096;
        b0 = nb0 + g*64;   b1 = nb1 + g*64;
        inBase = node_enc;
    }

    // ---- PRE-SYNC: stage all weights/biases (pure inputs), overlap bin ----
    {
        const float4* w = (const float4*)W0;
        float4* sw = (float4*)sW;
        #pragma unroll
        for (int k = 0; k < 4; k++) sw[tid + 256*k] = w[tid + 256*k];
        if (tid < 64) { sb0[tid] = b0[tid]; sb1[tid] = b1[tid]; }
    }
    float4 pw[4];
    {
        const float4* w = (const float4*)W1;
        #pragma unroll
        for (int k = 0; k < 4; k++) pw[k] = w[tid + 256*k];
    }
    if (isEdge) {
        if (tid < 64) sb2[tid] = eb2[g*64 + tid];
    } else {
        if (tid < 8) sb2[tid] = nb2[g*8 + tid];
    }

    // ---- wait for bin results ----
    cudaGridDependencySynchronize();

    int cnt = isEdge ? __ldcg(&g_ecnt[g]) : __ldcg(&g_ncnt[g]);
    if (base >= cnt) return;             // empty chunk: exit (PDL-safe)
    int ntask = min(32, cnt - base);

    // bucket + precomputed offset (single load each; no cni chain)
    if (tid < 32) {
        if (isEdge) {
            s_idx[tid] = __ldcg(&g_ebucket[g*NETASK + base + tid]);
            s_off[tid] = __ldcg(&g_eoff   [g*NETASK + base + tid]);
        } else {
            s_idx[tid] = __ldcg(&g_nbucket[g*NNODE + base + tid]);
            s_off[tid] = __ldcg(&g_noff   [g*NNODE + base + tid]);
        }
    }
    __syncthreads();

    // gather all 32 rows unconditionally (stale rows computed then discarded)
    {
        int s = tid >> 4, q = tid & 15;
        *(float4*)(sA + s*68 + q*4)      = *(const float4*)(inBase + (size_t)s_off[s]    + q*4);
        *(float4*)(sA + (s+16)*68 + q*4) = *(const float4*)(inBase + (size_t)s_off[s+16] + q*4);
    }
    __syncthreads();

    u64 a4[4];
    layer64(sA, sW, sb0, r0, colb, a4);              // layer 0
    __syncthreads();
    store_relu(sB, r0, colb, a4);
    {
        float4* sw = (float4*)sW;
        #pragma unroll
        for (int k = 0; k < 4; k++) sw[tid + 256*k] = pw[k];
    }
    if (isEdge) {
        const float4* w = (const float4*)(eW2 + g*4096);
        #pragma unroll
        for (int k = 0; k < 4; k++) pw[k] = w[tid + 256*k];
    } else {
        if (tid < 128) pw[0] = ((const float4*)(nW2 + g*512))[tid];
    }
    __syncthreads();

    layer64(sB, sW, sb1, r0, colb, a4);              // layer 1
    __syncthreads();
    store_relu(sA, r0, colb, a4);
    {
        float4* sw = (float4*)sW;
        if (isEdge) {
            #pragma unroll
            for (int k = 0; k < 4; k++) sw[tid + 256*k] = pw[k];
        } else {
            if (tid < 128) sw[tid] = pw[0];
        }
    }
    __syncthreads();

    if (isEdge) {                                     // layer 2 (edge, no relu)
        layer64(sA, sW, sb2, r0, colb, a4);
        float a, b, c, d;
        if (r0 < ntask) {
            unpack2(a4[0], a, b); unpack2(a4[1], c, d);
            *(float4*)(g_ef + (size_t)s_idx[r0]*64 + colb) = make_float4(a, b, c, d);
        }
        if (r0 + 4 < ntask) {
            unpack2(a4[2], a, b); unpack2(a4[3], c, d);
            *(float4*)(g_ef + (size_t)s_idx[r0+4]*64 + colb) = make_float4(a, b, c, d);
        }
    } else {                                          // layer 2 (node, 64->8)
        int row = tid >> 3, col = tid & 7;
        float a = sb2[col];
        const float* in = sA + row*68;
        #pragma unroll 16
        for (int d = 0; d < 64; d++) a += in[d] * sW[d*8 + col];
        if (row < ntask) g_nf[(size_t)s_idx[row]*8 + col] = a;
    }
    __threadfence();
    cudaTriggerProgrammaticLaunchCompletion();
}

// ---------------- kernel: assemble logpi (PDL; z-tail pre-sync) ----------
__global__ __launch_bounds__(256) void assemble_kernel(
    const int* __restrict__ cni, float* __restrict__ out, int writeZ)
{
    int tid = threadIdx.x;
    int sub = tid >> 6;
    int t   = tid & 63;
    int cq  = blockIdx.x * 4 + sub;

    __shared__ float e[4][192];
    __shared__ float nf[4][3][8];

    // PRE-SYNC: z tail (out region untouched by mlp)
    if (blockIdx.x == 0 && writeZ) {
        for (int m = tid; m < 512; m += 256) {
            int i = m >> 6, j = (m >> 3) & 7, k = m & 7;
            float* p = out + OUT_LOGPI + (size_t)m*3;
            p[0] = (float)i; p[1] = (float)j; p[2] = (float)k;
        }
    }

    cudaGridDependencySynchronize();

    // post-sync: safe to reset counters for the next replay (mlp grid done)
    if (blockIdx.x == 0) {
        if (tid < NET) g_ecnt[tid] = 0;
        if (tid < NT)  g_ncnt[tid] = 0;
    }

    size_t tbase = (size_t)cq * 192;
    e[sub][t]       = __ldcg(&g_ef[tbase + t]);
    e[sub][t + 64]  = __ldcg(&g_ef[tbase + t + 64]);
    e[sub][t + 128] = __ldcg(&g_ef[tbase + t + 128]);
    if (t < 24) {
        int k = t >> 3, zz = t & 7;
        int b = cq / NC;
        int node = clampi(cni[cq*3 + k], 0, NA-1);
        nf[sub][k][zz] = __ldcg(&g_nf[((size_t)b*NA + node)*8 + zz]);
    }
    __syncthreads();

    int z0 = t >> 3, z1 = t & 7;
    float bse = nf[sub][0][z0] + nf[sub][1][z1] + e[sub][z0*8 + z1];
    float r[8];
    #pragma unroll
    for (int z2 = 0; z2 < 8; z2++)
        r[z2] = bse + nf[sub][2][z2] + e[sub][64 + z0*8 + z2] + e[sub][128 + z1*8 + z2];
    float* op = out + (size_t)cq*512 + t*8;
    *(float4*)op       = make_float4(r[0], r[1], r[2], r[3]);
    *(float4*)(op + 4) = make_float4(r[4], r[5], r[6], r[7]);
}

// ---------------- launch ----------------
extern "C" void kernel_launch(void* const* d_in, const int* in_sizes, int n_in,
                              void* d_out, int out_size) {
    const int*   types    = (const int*)d_in[0];
    const float* node_enc = (const float*)d_in[1];
    const float* edge_enc = (const float*)d_in[2];
    const int*   cni      = (const int*)d_in[4];
    const float* nW0 = (const float*)d_in[6];
    const float* nb0 = (const float*)d_in[7];
    const float* nW1 = (const float*)d_in[8];
    const float* nb1 = (const float*)d_in[9];
    const float* nW2 = (const float*)d_in[10];
    const float* nb2 = (const float*)d_in[11];
    const float* eW0 = (const float*)d_in[12];
    const float* eb0 = (const float*)d_in[13];
    const float* eW1 = (const float*)d_in[14];
    const float* eb1 = (const float*)d_in[15];
    const float* eW2 = (const float*)d_in[16];
    const float* eb2 = (const float*)d_in[17];
    float* out = (float*)d_out;

    int writeZ = (out_size >= OUT_LOGPI + 512*3) ? 1 : 0;

    bin_tasks_kernel<<<28, 256>>>(types, cni, node_enc, edge_enc);

    cudaLaunchAttribute attr[1];
    attr[0].id = cudaLaunchAttributeProgrammaticStreamSerialization;
    attr[0].val.programmaticStreamSerializationAllowed = 1;

    {
        cudaLaunchConfig_t cfg = {};
        cfg.gridDim  = dim3(MLP_GRID, 1, 1);
        cfg.blockDim = dim3(256, 1, 1);
        cfg.stream   = 0;
        cfg.attrs    = attr;
        cfg.numAttrs = 1;
        cudaLaunchKernelEx(&cfg, mlp_kernel, node_enc, edge_enc,
                           nW0, nb0, nW1, nb1, nW2, nb2,
                           eW0, eb0, eW1, eb1, eW2, eb2);
    }
    {
        cudaLaunchConfig_t cfg = {};
        cfg.gridDim  = dim3(BS * NC / 4, 1, 1);
        cfg.blockDim = dim3(256, 1, 1);
        cfg.stream   = 0;
        cfg.attrs    = attr;
        cfg.numAttrs = 1;
        cudaLaunchKernelEx(&cfg, assemble_kernel, cni, out, writeZ);
    }
}

// round 9
// speedup vs baseline: 1.2810x; 1.0997x over previous
#include <cuda_runtime.h>

// Problem constants (fixed by setup_inputs)
#define BS   8
#define NA   128
#define NC   256
#define ZZ   8
#define NT   3
#define NET  9
#define NETASK (BS*NC*3)   // 6144 edge tasks
#define NNODE  (BS*NA)     // 1024 node tasks
#define NTASKS (NETASK + NNODE)  // 7168
#define OUT_LOGPI (BS*NC*ZZ*ZZ*ZZ)   // 1048576

typedef unsigned long long u64;

// ---------------- device scratch (no allocations allowed) ----------------
__device__ __align__(16) float g_nf[NNODE*ZZ];
__device__ __align__(16) float g_ef[NETASK*64];
__device__ int g_ecnt[NET];          // zero at load; re-zeroed by assemble
__device__ int g_ncnt[NT];
__device__ int g_ebucket[NET*NETASK];   // task id
__device__ int g_eoff[NET*NETASK];      // precomputed edge_enc offset
__device__ int g_nbucket[NT*NNODE];     // node id
__device__ int g_noff[NT*NNODE];        // precomputed node_enc offset

static __device__ __forceinline__ int clampi(int v, int lo, int hi) {
    return v < lo ? lo : (v > hi ? hi : v);
}

// ---------------- packed f32x2 helpers (FFMA2) ----------------
static __device__ __forceinline__ u64 pack2(float a, float b) {
    u64 r; asm("mov.b64 %0, {%1, %2};" : "=l"(r) : "f"(a), "f"(b)); return r;
}
static __device__ __forceinline__ void unpack2(u64 v, float& a, float& b) {
    asm("mov.b64 {%0, %1}, %2;" : "=f"(a), "=f"(b) : "l"(v));
}
static __device__ __forceinline__ void ffma2(u64& d, u64 a, u64 b) {
    asm("fma.rn.f32x2 %0, %1, %2, %0;" : "+l"(d) : "l"(a), "l"(b));
}
static __device__ __forceinline__ void prefetchL2(const void* p) {
    asm volatile("prefetch.global.L2 [%0];" :: "l"(p));
}

// ---------------- kernel: bin tasks (types staged in smem) ----------------
// grid 28 x 256: one task per thread. Plain launch (no PDL).
__global__ __launch_bounds__(256) void bin_tasks_kernel(
    const int* __restrict__ types, const int* __restrict__ cni,
    const float* __restrict__ node_enc, const float* __restrict__ edge_enc)
{
    __shared__ int sT[NNODE];
    __shared__ int h[12];
    __shared__ int basev[12];
    int tid = threadIdx.x;
    int t = blockIdx.x * 256 + tid;

    {
        int4 v = ((const int4*)types)[tid];
        ((int4*)sT)[tid] = v;
    }
    if (tid < 12) h[tid] = 0;
    __syncthreads();

    int bk = -1, val = 0, off = 0, pos = 0;
    const float* pfrow = 0;
    if (t < NETASK) {
        int b   = t / (NC*3);
        int rem = t - b*(NC*3);
        int c   = rem / 3;
        int p   = rem - 3*c;              // 0->(0,1) 1->(0,2) 2->(1,2)
        int a0  = (p == 2) ? 1 : 0;
        int a1  = (p == 0) ? 1 : 2;
        int i = clampi(cni[(b*NC + c)*3 + a0], 0, NA-1);
        int j = clampi(cni[(b*NC + c)*3 + a1], 0, NA-1);
        int ti = clampi(sT[b*NA + i], 0, NT-1);
        int tj = clampi(sT[b*NA + j], 0, NT-1);
        bk  = tj*3 + ti;                  // emask: pa==type[j], pb==type[i]
        val = t;
        off = ((b*NA + i)*NA + j) * 64;
        pfrow = edge_enc + (size_t)off;
    } else if (t < NTASKS) {
        int nn = t - NETASK;
        bk  = 9 + clampi(sT[nn], 0, NT-1);
        val = nn;
        off = nn * 64;
        pfrow = node_enc + (size_t)off;
    }
    if (bk >= 0) pos = atomicAdd(&h[bk], 1);
    __syncthreads();
    if (tid < 12 && h[tid] > 0) {
        basev[tid] = (tid < 9) ? atomicAdd(&g_ecnt[tid], h[tid])
                               : atomicAdd(&g_ncnt[tid-9], h[tid]);
    }
    __syncthreads();
    if (bk >= 0) {
        int base = basev[bk];
        if (bk < 9) {
            g_ebucket[bk*NETASK + base + pos] = val;
            g_eoff   [bk*NETASK + base + pos] = off;
        } else {
            g_nbucket[(bk-9)*NNODE + base + pos] = val;
            g_noff   [(bk-9)*NNODE + base + pos] = off;
        }
        // warm L2 with this task's 256B input row for the mlp gather
        prefetchL2(pfrow);
        prefetchL2(pfrow + 32);
    }
}

// ---------------- 32x64 @ 64x64 layer, 256 thr, 2 rows x 4 cols/thread ----
static __device__ __forceinline__ void layer64(const float* __restrict__ sIn,
                                               const float* __restrict__ sW,
                                               const float* __restrict__ sb,
                                               int r0, int colb, u64 acc[4]) {
    ulonglong2 bv = *(const ulonglong2*)(sb + colb);
    acc[0] = bv.x; acc[1] = bv.y; acc[2] = bv.x; acc[3] = bv.y;
    const float* in0 = sIn + r0*68;
    const float* in1 = sIn + (r0+4)*68;
    #pragma unroll
    for (int d0 = 0; d0 < 64; d0 += 4) {
        float4 x0 = *(const float4*)(in0 + d0);
        float4 x1 = *(const float4*)(in1 + d0);
        {
            ulonglong2 w = *(const ulonglong2*)(sW + (d0+0)*64 + colb);
            u64 a0 = pack2(x0.x, x0.x), a1 = pack2(x1.x, x1.x);
            ffma2(acc[0], a0, w.x); ffma2(acc[1], a0, w.y);
            ffma2(acc[2], a1, w.x); ffma2(acc[3], a1, w.y);
        }
        {
            ulonglong2 w = *(const ulonglong2*)(sW + (d0+1)*64 + colb);
            u64 a0 = pack2(x0.y, x0.y), a1 = pack2(x1.y, x1.y);
            ffma2(acc[0], a0, w.x); ffma2(acc[1], a0, w.y);
            ffma2(acc[2], a1, w.x); ffma2(acc[3], a1, w.y);
        }
        {
            ulonglong2 w = *(const ulonglong2*)(sW + (d0+2)*64 + colb);
            u64 a0 = pack2(x0.z, x0.z), a1 = pack2(x1.z, x1.z);
            ffma2(acc[0], a0, w.x); ffma2(acc[1], a0, w.y);
            ffma2(acc[2], a1, w.x); ffma2(acc[3], a1, w.y);
        }
        {
            ulonglong2 w = *(const ulonglong2*)(sW + (d0+3)*64 + colb);
            u64 a0 = pack2(x0.w, x0.w), a1 = pack2(x1.w, x1.w);
            ffma2(acc[0], a0, w.x); ffma2(acc[1], a0, w.y);
            ffma2(acc[2], a1, w.x); ffma2(acc[3], a1, w.y);
        }
    }
}

static __device__ __forceinline__ void store_relu(float* __restrict__ sOut,
                                                  int r0, int colb, const u64 acc[4]) {
    float a, b, c, d;
    unpack2(acc[0], a, b); unpack2(acc[1], c, d);
    *(float4*)(sOut + r0*68 + colb) =
        make_float4(fmaxf(a,0.f), fmaxf(b,0.f), fmaxf(c,0.f), fmaxf(d,0.f));
    unpack2(acc[2], a, b); unpack2(acc[3], c, d);
    *(float4*)(sOut + (r0+4)*68 + colb) =
        make_float4(fmaxf(a,0.f), fmaxf(b,0.f), fmaxf(c,0.f), fmaxf(d,0.f));
}

// ---------------- combined node+edge MLP kernel (R3 structure) -------------
// grid 240; CTA maps itself to (type, chunk) via prefix scan of bucket counts.
__global__ __launch_bounds__(256) void mlp_kernel(
    const float* __restrict__ node_enc, const float* __restrict__ edge_enc,
    const float* __restrict__ nW0, const float* __restrict__ nb0,
    const float* __restrict__ nW1, const float* __restrict__ nb1,
    const float* __restrict__ nW2, const float* __restrict__ nb2,
    const float* __restrict__ eW0, const float* __restrict__ eb0,
    const float* __restrict__ eW1, const float* __restrict__ eb1,
    const float* __restrict__ eW2, const float* __restrict__ eb2)
{
    // ---- role mapping (uniform across threads) ----
    int bid = blockIdx.x;
    int g = -1, chunk = 0, acc = 0, cnt = 0;
    bool isEdge = true;
    #pragma unroll
    for (int t = 0; t < NET; t++) {
        int n = g_ecnt[t];
        int c = (n + 31) >> 5;
        if (g < 0 && bid < acc + c) { g = t; chunk = bid - acc; cnt = n; }
        acc += c;
    }
    if (g < 0) {
        isEdge = false;
        int nb = bid - acc; acc = 0;
        #pragma unroll
        for (int t = 0; t < NT; t++) {
            int n = g_ncnt[t];
            int c = (n + 31) >> 5;
            if (g < 0 && nb < acc + c) { g = t; chunk = nb - acc; cnt = n; }
            acc += c;
        }
        if (g < 0) return;
    }
    int base  = chunk * 32;
    int ntask = min(32, cnt - base);

    __shared__ __align__(16) float sW[64*64];
    __shared__ __align__(16) float sb0[64], sb1[64], sb2[64];
    __shared__ __align__(16) float sA[32*68];
    __shared__ __align__(16) float sB[32*68];
    __shared__ int s_idx[32];
    __shared__ int s_off[32];

    int tid  = threadIdx.x;
    int warp = tid >> 5, lane = tid & 31;
    int colb = (warp & 1) * 32 + (lane & 7) * 4;
    int r0   = (warp >> 1) * 8 + (lane >> 3);

    const float *W0, *W1, *b0, *b1, *inBase;
    if (isEdge) {
        W0 = eW0 + g*4096; W1 = eW1 + g*4096;
        b0 = eb0 + g*64;   b1 = eb1 + g*64;
        inBase = edge_enc;
        if (tid < 32) {
            s_idx[tid] = g_ebucket[g*NETASK + base + min(tid, ntask-1)];
            s_off[tid] = g_eoff   [g*NETASK + base + min(tid, ntask-1)];
        }
    } else {
        W0 = nW0 + g*4096; W1 = nW1 + g*4096;
        b0 = nb0 + g*64;   b1 = nb1 + g*64;
        inBase = node_enc;
        if (tid < 32) {
            s_idx[tid] = g_nbucket[g*NNODE + base + min(tid, ntask-1)];
            s_off[tid] = g_noff   [g*NNODE + base + min(tid, ntask-1)];
        }
    }

    // stage W0 + biases
    {
        const float4* w = (const float4*)W0;
        float4* sw = (float4*)sW;
        #pragma unroll
        for (int k = 0; k < 4; k++) sw[tid + 256*k] = w[tid + 256*k];
        if (tid < 64) { sb0[tid] = b0[tid]; sb1[tid] = b1[tid]; }
    }
    __syncthreads();

    // gather inputs (L2-warm), prefetch W1 into regs
    float4 pw[4];
    {
        const float4* w = (const float4*)W1;
        #pragma unroll
        for (int k = 0; k < 4; k++) pw[k] = w[tid + 256*k];
    }
    {
        int s = tid >> 4, q = tid & 15;
        *(float4*)(sA + s*68 + q*4)      = *(const float4*)(inBase + (size_t)s_off[s]    + q*4);
        *(float4*)(sA + (s+16)*68 + q*4) = *(const float4*)(inBase + (size_t)s_off[s+16] + q*4);
    }
    __syncthreads();

    u64 a4[4];
    layer64(sA, sW, sb0, r0, colb, a4);              // layer 0
    __syncthreads();
    store_relu(sB, r0, colb, a4);
    {
        float4* sw = (float4*)sW;
        #pragma unroll
        for (int k = 0; k < 4; k++) sw[tid + 256*k] = pw[k];
    }
    if (isEdge) {
        const float4* w = (const float4*)(eW2 + g*4096);
        #pragma unroll
        for (int k = 0; k < 4; k++) pw[k] = w[tid + 256*k];
        if (tid < 64) sb2[tid] = eb2[g*64 + tid];
    } else {
        if (tid < 128) pw[0] = ((const float4*)(nW2 + g*512))[tid];
        if (tid < 8)   sb2[tid] = nb2[g*8 + tid];
    }
    __syncthreads();

    layer64(sB, sW, sb1, r0, colb, a4);              // layer 1
    __syncthreads();
    store_relu(sA, r0, colb, a4);
    {
        float4* sw = (float4*)sW;
        if (isEdge) {
            #pragma unroll
            for (int k = 0; k < 4; k++) sw[tid + 256*k] = pw[k];
        } else {
            if (tid < 128) sw[tid] = pw[0];
        }
    }
    __syncthreads();

    if (isEdge) {                                     // layer 2 (edge, no relu)
        layer64(sA, sW, sb2, r0, colb, a4);
        float a, b, c, d;
        if (r0 < ntask) {
            unpack2(a4[0], a, b); unpack2(a4[1], c, d);
            *(float4*)(g_ef + (size_t)s_idx[r0]*64 + colb) = make_float4(a, b, c, d);
        }
        if (r0 + 4 < ntask) {
            unpack2(a4[2], a, b); unpack2(a4[3], c, d);
            *(float4*)(g_ef + (size_t)s_idx[r0+4]*64 + colb) = make_float4(a, b, c, d);
        }
    } else {                                          // layer 2 (node, 64->8)
        int row = tid >> 3, col = tid & 7;
        float a = sb2[col];
        const float* in = sA + row*68;
        #pragma unroll 16
        for (int d = 0; d < 64; d++) a += in[d] * sW[d*8 + col];
        if (row < ntask) g_nf[(size_t)s_idx[row]*8 + col] = a;
    }
    __threadfence();
    cudaTriggerProgrammaticLaunchCompletion();
}

// ---------------- kernel: assemble logpi (PDL; z-tail pre-sync) ----------
__global__ __launch_bounds__(256) void assemble_kernel(
    const int* __restrict__ cni, float* __restrict__ out, int writeZ)
{
    int tid = threadIdx.x;
    int sub = tid >> 6;
    int t   = tid & 63;
    int cq  = blockIdx.x * 4 + sub;

    __shared__ float e[4][192];
    __shared__ float nf[4][3][8];

    // PRE-SYNC: z tail (out region untouched by mlp) — tiny, no contention
    if (blockIdx.x == 0 && writeZ) {
        for (int m = tid; m < 512; m += 256) {
            int i = m >> 6, j = (m >> 3) & 7, k = m & 7;
            float* p = out + OUT_LOGPI + (size_t)m*3;
            p[0] = (float)i; p[1] = (float)j; p[2] = (float)k;
        }
    }

    cudaGridDependencySynchronize();

    // post-sync: safe to reset counters for the next replay (mlp grid done)
    if (blockIdx.x == 0) {
        if (tid < NET) g_ecnt[tid] = 0;
        if (tid < NT)  g_ncnt[tid] = 0;
    }

    size_t tbase = (size_t)cq * 192;
    e[sub][t]       = __ldcg(&g_ef[tbase + t]);
    e[sub][t + 64]  = __ldcg(&g_ef[tbase + t + 64]);
    e[sub][t + 128] = __ldcg(&g_ef[tbase + t + 128]);
    if (t < 24) {
        int k = t >> 3, zz = t & 7;
        int b = cq / NC;
        int node = clampi(cni[cq*3 + k], 0, NA-1);
        nf[sub][k][zz] = __ldcg(&g_nf[((size_t)b*NA + node)*8 + zz]);
    }
    __syncthreads();

    int z0 = t >> 3, z1 = t & 7;
    float bse = nf[sub][0][z0] + nf[sub][1][z1] + e[sub][z0*8 + z1];
    float r[8];
    #pragma unroll
    for (int z2 = 0; z2 < 8; z2++)
        r[z2] = bse + nf[sub][2][z2] + e[sub][64 + z0*8 + z2] + e[sub][128 + z1*8 + z2];
    float* op = out + (size_t)cq*512 + t*8;
    *(float4*)op       = make_float4(r[0], r[1], r[2], r[3]);
    *(float4*)(op + 4) = make_float4(r[4], r[5], r[6], r[7]);
}

// ---------------- launch ----------------
extern "C" void kernel_launch(void* const* d_in, const int* in_sizes, int n_in,
                              void* d_out, int out_size) {
    const int*   types    = (const int*)d_in[0];
    const float* node_enc = (const float*)d_in[1];
    const float* edge_enc = (const float*)d_in[2];
    const int*   cni      = (const int*)d_in[4];
    const float* nW0 = (const float*)d_in[6];
    const float* nb0 = (const float*)d_in[7];
    const float* nW1 = (const float*)d_in[8];
    const float* nb1 = (const float*)d_in[9];
    const float* nW2 = (const float*)d_in[10];
    const float* nb2 = (const float*)d_in[11];
    const float* eW0 = (const float*)d_in[12];
    const float* eb0 = (const float*)d_in[13];
    const float* eW1 = (const float*)d_in[14];
    const float* eb1 = (const float*)d_in[15];
    const float* eW2 = (const float*)d_in[16];
    const float* eb2 = (const float*)d_in[17];
    float* out = (float*)d_out;

    int writeZ = (out_size >= OUT_LOGPI + 512*3) ? 1 : 0;

    // plain launches for bin and mlp (bin->mlp PDL measured harmful)
    bin_tasks_kernel<<<28, 256>>>(types, cni, node_enc, edge_enc);
    mlp_kernel<<<240, 256>>>(node_enc, edge_enc,
                             nW0, nb0, nW1, nb1, nW2, nb2,
                             eW0, eb0, eW1, eb1, eW2, eb2);

    // PDL only on mlp->assemble (pre-sync work is tiny)
    cudaLaunchAttribute attr[1];
    attr[0].id = cudaLaunchAttributeProgrammaticStreamSerialization;
    attr[0].val.programmaticStreamSerializationAllowed = 1;
    cudaLaunchConfig_t cfg = {};
    cfg.gridDim  = dim3(BS * NC / 4, 1, 1);
    cfg.blockDim = dim3(256, 1, 1);
    cfg.stream   = 0;
    cfg.attrs    = attr;
    cfg.numAttrs = 1;
    cudaLaunchKernelEx(&cfg, assemble_kernel, cni, out, writeZ);
}